// round 2
// baseline (speedup 1.0000x reference)
#include <cuda_runtime.h>
#include <math.h>

// ---------------------------------------------------------------------------
// Problem constants
// ---------------------------------------------------------------------------
constexpr int B  = 512;
constexpr int S  = 64;
constexpr int T  = 120;
constexpr int E  = 192;
constexpr int H  = 256;
constexpr int EH = 512;   // 2H
constexpr int V  = 512;   // OUT_V
constexpr int G4 = 1024;  // 4H

#define DINL __device__ __forceinline__

// ---------------------------------------------------------------------------
// Scratch (static device globals -- allocation-free at launch time)
// ---------------------------------------------------------------------------
__device__ float g_Gin[(size_t)2 * B * S * G4];   // enc input gates (f, b), bias folded
__device__ float g_decEmb[(size_t)B * T * E];     // gathered teacher-forced dec embeddings
__device__ float g_encOuts[(size_t)B * S * EH];   // encoder outputs [b][s][2H]
__device__ float g_encProj[(size_t)B * S * H];    // enc_outs @ attn_We^T + attn_b
__device__ float g_hEnc[2 * 2 * B * H];           // [dir][ping][B][H]
__device__ float g_cEnc[2 * B * H];               // [dir][B][H]
__device__ float g_hDec[2 * B * H];               // [ping][B][H]
__device__ float g_cDec[B * H];
__device__ float g_ctx[B * EH];
__device__ float g_qp[B * H];                     // h @ attn_Wh^T

DINL float sigmoidf_(float x) { return 1.0f / (1.0f + expf(-x)); }

// ---------------------------------------------------------------------------
// zero fill
// ---------------------------------------------------------------------------
__global__ void zero_kernel(float* p, int n) {
    for (int i = blockIdx.x * blockDim.x + threadIdx.x; i < n; i += gridDim.x * blockDim.x)
        p[i] = 0.0f;
}

// ---------------------------------------------------------------------------
// Gather teacher-forced decoder embeddings: decEmb[b*T+t] = dec_emb[tok(b,t)]
// tok = (t==0) ? SOS(=1) : trg[b*T + t - 1]
// ---------------------------------------------------------------------------
__global__ __launch_bounds__(192) void dec_embed_gather_kernel(
    const int* __restrict__ trg,
    const float* __restrict__ dec_emb,
    float* __restrict__ decEmb)
{
    const int m = blockIdx.x;           // 0 .. B*T-1
    const int t = m % T;
    const int tok = (t == 0) ? 1 : trg[m - 1];
    decEmb[(size_t)m * E + threadIdx.x] = dec_emb[(size_t)tok * E + threadIdx.x];
}

// ---------------------------------------------------------------------------
// Embedding-gathered GEMM:  C[m][n] = sum_k emb[toks[m]][k] * W[n][k]  + bias[n]
// K = 192 fixed (encoder src path).
// ---------------------------------------------------------------------------
__global__ __launch_bounds__(256) void embed_gemm_kernel(
    const int* __restrict__ toks,
    const float* __restrict__ emb,
    const float* __restrict__ W, int ldW,
    const float* __restrict__ bias,
    float* __restrict__ C, int ldC)
{
    __shared__ float As[64][33];
    __shared__ float Bs[64][33];
    __shared__ int   stok[64];

    const int tid = threadIdx.x;
    const int m0 = blockIdx.x * 64;
    const int n0 = blockIdx.y * 64;
    const int ty = tid / 16, tx = tid % 16;

    if (tid < 64) stok[tid] = toks[m0 + tid];
    __syncthreads();

    float acc[4][4] = {};

    for (int kc = 0; kc < E; kc += 32) {
        #pragma unroll
        for (int idx = tid; idx < 512; idx += 256) {
            int r = idx >> 3, c4 = idx & 7;
            float4 v = *(const float4*)(emb + (size_t)stok[r] * E + kc + c4 * 4);
            As[r][c4 * 4 + 0] = v.x; As[r][c4 * 4 + 1] = v.y;
            As[r][c4 * 4 + 2] = v.z; As[r][c4 * 4 + 3] = v.w;
        }
        #pragma unroll
        for (int idx = tid; idx < 512; idx += 256) {
            int r = idx >> 3, c4 = idx & 7;
            float4 v = *(const float4*)(W + (size_t)(n0 + r) * ldW + kc + c4 * 4);
            Bs[r][c4 * 4 + 0] = v.x; Bs[r][c4 * 4 + 1] = v.y;
            Bs[r][c4 * 4 + 2] = v.z; Bs[r][c4 * 4 + 3] = v.w;
        }
        __syncthreads();
        #pragma unroll
        for (int k = 0; k < 32; k++) {
            float a[4], b[4];
            #pragma unroll
            for (int i = 0; i < 4; i++) a[i] = As[ty * 4 + i][k];
            #pragma unroll
            for (int j = 0; j < 4; j++) b[j] = Bs[tx * 4 + j][k];
            #pragma unroll
            for (int i = 0; i < 4; i++)
                #pragma unroll
                for (int j = 0; j < 4; j++) acc[i][j] += a[i] * b[j];
        }
        __syncthreads();
    }

    #pragma unroll
    for (int i = 0; i < 4; i++)
        #pragma unroll
        for (int j = 0; j < 4; j++) {
            int m = m0 + ty * 4 + i, n = n0 + tx * 4 + j;
            C[(size_t)m * ldC + n] = acc[i][j] + bias[n];
        }
}

// ---------------------------------------------------------------------------
// Generic fp32 GEMM:  C = act( [A0|A1|A2] @ W^T + bias + Cadd )
// A split into up to three K-segments (row-major, K-contiguous).
// W row-major [N][ldW], K-contiguous across all segments.
// act: 0 = none, 1 = tanh
// ---------------------------------------------------------------------------
template <int BM, int BN>
__global__ __launch_bounds__((BM / 4) * (BN / 4)) void gemm_kernel(
    const float* __restrict__ A0, int ldA0, int K0,
    const float* __restrict__ A1, int ldA1, int K1,
    const float* __restrict__ A2, int ldA2, int K2,
    const float* __restrict__ W, int ldW,
    const float* __restrict__ bias,
    const float* __restrict__ Cadd, int ldAdd,
    int act,
    float* __restrict__ C, int ldC)
{
    constexpr int NT = (BM / 4) * (BN / 4);
    __shared__ float As[BM][33];
    __shared__ float Bs[BN][33];

    const int tid = threadIdx.x;
    const int m0 = blockIdx.x * BM;
    const int n0 = blockIdx.y * BN;
    const int ty = tid / (BN / 4), tx = tid % (BN / 4);

    float acc[4][4] = {};
    const int K = K0 + K1 + K2;

    for (int kc = 0; kc < K; kc += 32) {
        const float* Ab; int ldA, kk0;
        if (kc < K0)            { Ab = A0; ldA = ldA0; kk0 = kc; }
        else if (kc < K0 + K1)  { Ab = A1; ldA = ldA1; kk0 = kc - K0; }
        else                    { Ab = A2; ldA = ldA2; kk0 = kc - K0 - K1; }

        #pragma unroll
        for (int idx = tid; idx < BM * 8; idx += NT) {
            int r = idx >> 3, c4 = idx & 7;
            float4 v = *(const float4*)(Ab + (size_t)(m0 + r) * ldA + kk0 + c4 * 4);
            As[r][c4 * 4 + 0] = v.x; As[r][c4 * 4 + 1] = v.y;
            As[r][c4 * 4 + 2] = v.z; As[r][c4 * 4 + 3] = v.w;
        }
        #pragma unroll
        for (int idx = tid; idx < BN * 8; idx += NT) {
            int r = idx >> 3, c4 = idx & 7;
            float4 v = *(const float4*)(W + (size_t)(n0 + r) * ldW + kc + c4 * 4);
            Bs[r][c4 * 4 + 0] = v.x; Bs[r][c4 * 4 + 1] = v.y;
            Bs[r][c4 * 4 + 2] = v.z; Bs[r][c4 * 4 + 3] = v.w;
        }
        __syncthreads();
        #pragma unroll
        for (int k = 0; k < 32; k++) {
            float a[4], b[4];
            #pragma unroll
            for (int i = 0; i < 4; i++) a[i] = As[ty * 4 + i][k];
            #pragma unroll
            for (int j = 0; j < 4; j++) b[j] = Bs[tx * 4 + j][k];
            #pragma unroll
            for (int i = 0; i < 4; i++)
                #pragma unroll
                for (int j = 0; j < 4; j++) acc[i][j] += a[i] * b[j];
        }
        __syncthreads();
    }

    #pragma unroll
    for (int i = 0; i < 4; i++)
        #pragma unroll
        for (int j = 0; j < 4; j++) {
            int m = m0 + ty * 4 + i, n = n0 + tx * 4 + j;
            float vv = acc[i][j];
            if (bias) vv += bias[n];
            if (Cadd) vv += Cadd[(size_t)m * ldAdd + n];
            if (act == 1) vv = tanhf(vv);
            C[(size_t)m * ldC + n] = vv;
        }
}

// ---------------------------------------------------------------------------
// Fused LSTM step:
//   gates[m][g*256+j] = Gadd[m][g*256+j](opt) + bias[g*256+j](opt)
//                     + sum_k [A0|A1|A2][m][k] * [Wseg][g*256+j][k]
//   c' = sig(f)*c + sig(i)*tanh(g);  h' = sig(o)*tanh(c')
// Block computes BM rows x 32 j-columns x all 4 gates.
// blockIdx.z selects the direction parameter set (encoder fwd/bwd fused).
// ---------------------------------------------------------------------------
struct LstmDirArgs {
    const float* A0; int ldA0, K0;
    const float* A1; int ldA1, K1;
    const float* A2; int ldA2, K2;
    const float* W0; int ldW0;   // covers K-range [0, K0)
    const float* W1; int ldW1;   // covers K-range [K0, K0+K1)
    const float* W2; int ldW2;   // covers K-range [K0+K1, K)
    const float* G;  int ldG;    // optional precomputed gate term (may be null)
    const float* bias;           // optional [4H] bias (may be null)
    float* c;                    // [M][256] in/out
    float* h;                    // [M][256] out (ping buffer)
    float* h2; int ldH2;         // optional second h write (enc_outs slice)
};
struct LstmArgs2 { LstmDirArgs d[2]; };

template <int BM>
__global__ __launch_bounds__((BM / 4) * 16) void lstm_step_kernel(LstmArgs2 aa)
{
    const LstmDirArgs a = aa.d[blockIdx.z];
    constexpr int NT = (BM / 4) * 16;
    __shared__ float As[BM][33];
    __shared__ float Ws[4][32][33];

    const int tid = threadIdx.x;
    const int m0 = blockIdx.x * BM;
    const int j0 = blockIdx.y * 32;
    const int ty = tid / 16, tx = tid % 16;

    float acc[4][2][4] = {};   // [mi][jj][gate]
    const int K = a.K0 + a.K1 + a.K2;

    for (int kc = 0; kc < K; kc += 32) {
        const float* Ab; int ldA, kk0;
        const float* Wb; int ldWb;
        if (kc < a.K0) {
            Ab = a.A0; ldA = a.ldA0; kk0 = kc;
            Wb = a.W0; ldWb = a.ldW0;
        } else if (kc < a.K0 + a.K1) {
            Ab = a.A1; ldA = a.ldA1; kk0 = kc - a.K0;
            Wb = a.W1; ldWb = a.ldW1;
        } else {
            Ab = a.A2; ldA = a.ldA2; kk0 = kc - a.K0 - a.K1;
            Wb = a.W2; ldWb = a.ldW2;
        }
        #pragma unroll
        for (int idx = tid; idx < BM * 8; idx += NT) {
            int r = idx >> 3, c4 = idx & 7;
            float4 v = *(const float4*)(Ab + (size_t)(m0 + r) * ldA + kk0 + c4 * 4);
            As[r][c4 * 4 + 0] = v.x; As[r][c4 * 4 + 1] = v.y;
            As[r][c4 * 4 + 2] = v.z; As[r][c4 * 4 + 3] = v.w;
        }
        #pragma unroll
        for (int idx = tid; idx < 1024; idx += NT) {
            int g = idx >> 8, rem = idx & 255, j = rem >> 3, c4 = rem & 7;
            int n = g * 256 + j0 + j;
            float4 v = *(const float4*)(Wb + (size_t)n * ldWb + kk0 + c4 * 4);
            Ws[g][j][c4 * 4 + 0] = v.x; Ws[g][j][c4 * 4 + 1] = v.y;
            Ws[g][j][c4 * 4 + 2] = v.z; Ws[g][j][c4 * 4 + 3] = v.w;
        }
        __syncthreads();
        #pragma unroll
        for (int k = 0; k < 32; k++) {
            float av[4];
            #pragma unroll
            for (int mi = 0; mi < 4; mi++) av[mi] = As[ty * 4 + mi][k];
            #pragma unroll
            for (int jj = 0; jj < 2; jj++) {
                #pragma unroll
                for (int g = 0; g < 4; g++) {
                    float w = Ws[g][tx * 2 + jj][k];
                    #pragma unroll
                    for (int mi = 0; mi < 4; mi++) acc[mi][jj][g] += av[mi] * w;
                }
            }
        }
        __syncthreads();
    }

    #pragma unroll
    for (int mi = 0; mi < 4; mi++) {
        #pragma unroll
        for (int jj = 0; jj < 2; jj++) {
            int m = m0 + ty * 4 + mi;
            int j = j0 + tx * 2 + jj;
            float gi = acc[mi][jj][0];
            float gf = acc[mi][jj][1];
            float gg = acc[mi][jj][2];
            float go = acc[mi][jj][3];
            if (a.G) {
                const float* gr = a.G + (size_t)m * a.ldG;
                gi += gr[j]; gf += gr[256 + j]; gg += gr[512 + j]; go += gr[768 + j];
            }
            if (a.bias) {
                gi += a.bias[j];       gf += a.bias[256 + j];
                gg += a.bias[512 + j]; go += a.bias[768 + j];
            }
            float cold = a.c[m * 256 + j];
            float cn = sigmoidf_(gf) * cold + sigmoidf_(gi) * tanhf(gg);
            float hn = sigmoidf_(go) * tanhf(cn);
            a.c[m * 256 + j] = cn;
            a.h[m * 256 + j] = hn;
            if (a.h2) a.h2[(size_t)m * a.ldH2 + j] = hn;
        }
    }
}

// ---------------------------------------------------------------------------
// Attention step (per-batch-row block, 128 threads):
//   score[s] = sum_j v[j] * tanh(qp[b][j] + encProj[b][s][j])    (masked)
//   aw = softmax(score);  ctx[b] = sum_s aw[s] * encOuts[b][s][:]
// ---------------------------------------------------------------------------
__global__ __launch_bounds__(128) void attn_kernel(
    const int* __restrict__ src,
    const float* __restrict__ qp,
    const float* __restrict__ encProj,
    const float* __restrict__ encOuts,
    const float* __restrict__ v,
    float* __restrict__ ctx)
{
    const int b = blockIdx.x;
    const int tid = threadIdx.x;
    __shared__ float qpv[256];
    __shared__ float vv[256];
    __shared__ float sc[64];

    qpv[tid]       = qp[b * 256 + tid];
    qpv[tid + 128] = qp[b * 256 + 128 + tid];
    vv[tid]        = v[tid];
    vv[tid + 128]  = v[tid + 128];
    __syncthreads();

    const int w = tid >> 5, lane = tid & 31;
    #pragma unroll 4
    for (int i = 0; i < 16; i++) {
        int s = w * 16 + i;
        const float* ep = encProj + (size_t)(b * 64 + s) * 256;
        float sum = 0.0f;
        #pragma unroll
        for (int r = 0; r < 8; r++) {
            int j = lane + r * 32;
            sum += tanhf(qpv[j] + ep[j]) * vv[j];
        }
        #pragma unroll
        for (int off = 16; off > 0; off >>= 1)
            sum += __shfl_xor_sync(0xffffffffu, sum, off);
        if (lane == 0)
            sc[s] = (src[b * 64 + s] != 0) ? sum : -1e9f;
    }
    __syncthreads();

    if (tid < 32) {
        float a = sc[tid], b2 = sc[tid + 32];
        float mx = fmaxf(a, b2);
        #pragma unroll
        for (int off = 16; off > 0; off >>= 1)
            mx = fmaxf(mx, __shfl_xor_sync(0xffffffffu, mx, off));
        float ea = expf(a - mx), eb = expf(b2 - mx);
        float sm = ea + eb;
        #pragma unroll
        for (int off = 16; off > 0; off >>= 1)
            sm += __shfl_xor_sync(0xffffffffu, sm, off);
        float inv = 1.0f / sm;
        sc[tid] = ea * inv;
        sc[tid + 32] = eb * inv;
    }
    __syncthreads();

    const int kk = tid * 4;
    float4 accv = make_float4(0.f, 0.f, 0.f, 0.f);
    #pragma unroll 4
    for (int s = 0; s < 64; s++) {
        float wgt = sc[s];
        float4 e = *(const float4*)(encOuts + (size_t)(b * 64 + s) * 512 + kk);
        accv.x += wgt * e.x; accv.y += wgt * e.y;
        accv.z += wgt * e.z; accv.w += wgt * e.w;
    }
    *(float4*)(ctx + (size_t)b * 512 + kk) = accv;
}

// ---------------------------------------------------------------------------
// Host orchestration
// ---------------------------------------------------------------------------
extern "C" void kernel_launch(void* const* d_in, const int* in_sizes, int n_in,
                              void* d_out, int out_size)
{
    const int*   src       = (const int*)d_in[0];
    // d_in[1] = src_len (unused: all full-length; mask comes from src != 0)
    const int*   trg       = (const int*)d_in[2];
    const float* enc_emb   = (const float*)d_in[3];
    const float* enc_Wih_f = (const float*)d_in[4];
    const float* enc_Whh_f = (const float*)d_in[5];
    const float* enc_b_f   = (const float*)d_in[6];
    const float* enc_Wih_b = (const float*)d_in[7];
    const float* enc_Whh_b = (const float*)d_in[8];
    const float* enc_b_b   = (const float*)d_in[9];
    const float* enc_fc_W  = (const float*)d_in[10];
    const float* enc_fc_b  = (const float*)d_in[11];
    const float* dec_emb   = (const float*)d_in[12];
    const float* dec_Wih   = (const float*)d_in[13];
    const float* dec_Whh   = (const float*)d_in[14];
    const float* dec_b     = (const float*)d_in[15];
    const float* attn_W    = (const float*)d_in[16];
    const float* attn_b    = (const float*)d_in[17];
    const float* attn_v    = (const float*)d_in[18];
    const float* out_W     = (const float*)d_in[19];
    const float* out_b     = (const float*)d_in[20];
    float* out = (float*)d_out;

    float *Gin, *decEmb, *encOuts, *encProj, *hEnc, *cEnc, *hDec, *cDec, *ctx, *qp;
    cudaGetSymbolAddress((void**)&Gin,     g_Gin);
    cudaGetSymbolAddress((void**)&decEmb,  g_decEmb);
    cudaGetSymbolAddress((void**)&encOuts, g_encOuts);
    cudaGetSymbolAddress((void**)&encProj, g_encProj);
    cudaGetSymbolAddress((void**)&hEnc,    g_hEnc);
    cudaGetSymbolAddress((void**)&cEnc,    g_cEnc);
    cudaGetSymbolAddress((void**)&hDec,    g_hDec);
    cudaGetSymbolAddress((void**)&cDec,    g_cDec);
    cudaGetSymbolAddress((void**)&ctx,     g_ctx);
    cudaGetSymbolAddress((void**)&qp,      g_qp);

    const size_t GINSZ = (size_t)B * S * G4;      // per-direction Gin stride
    const int    BH    = B * H;

    // ---- zero recurrent state -------------------------------------------------
    zero_kernel<<<256, 256>>>(hEnc, 4 * BH);
    zero_kernel<<<256, 256>>>(cEnc, 2 * BH);
    zero_kernel<<<128, 256>>>(cDec, BH);

    // ---- precompute: encoder input gates + decoder embedding gather -----------
    embed_gemm_kernel<<<dim3(B * S / 64, G4 / 64), 256>>>(
        src, enc_emb, enc_Wih_f, E, enc_b_f, Gin, G4);
    embed_gemm_kernel<<<dim3(B * S / 64, G4 / 64), 256>>>(
        src, enc_emb, enc_Wih_b, E, enc_b_b, Gin + GINSZ, G4);
    dec_embed_gather_kernel<<<B * T, 192>>>(trg, dec_emb, decEmb);

    // ---- encoder recurrence (fwd + bwd fused via blockIdx.z) ------------------
    for (int t = 0; t < S; t++) {
        int p = t & 1;
        LstmArgs2 la;
        // forward
        la.d[0].A0 = hEnc + (size_t)(0 * 2 + p) * BH; la.d[0].ldA0 = H; la.d[0].K0 = H;
        la.d[0].A1 = nullptr; la.d[0].ldA1 = 0; la.d[0].K1 = 0;
        la.d[0].A2 = nullptr; la.d[0].ldA2 = 0; la.d[0].K2 = 0;
        la.d[0].W0 = enc_Whh_f; la.d[0].ldW0 = H;
        la.d[0].W1 = nullptr;   la.d[0].ldW1 = 0;
        la.d[0].W2 = nullptr;   la.d[0].ldW2 = 0;
        la.d[0].G = Gin + (size_t)t * G4; la.d[0].ldG = S * G4;
        la.d[0].bias = nullptr;
        la.d[0].c = cEnc;
        la.d[0].h = hEnc + (size_t)(0 * 2 + (1 - p)) * BH;
        la.d[0].h2 = encOuts + (size_t)t * EH;   // enc_outs[:, t, 0:256]
        la.d[0].ldH2 = S * EH;
        // backward (input at s = S-1-t, output slot s = S-1-t, cols 256:512)
        int sb = S - 1 - t;
        la.d[1] = la.d[0];
        la.d[1].A0 = hEnc + (size_t)(1 * 2 + p) * BH;
        la.d[1].W0 = enc_Whh_b;
        la.d[1].G = Gin + GINSZ + (size_t)sb * G4;
        la.d[1].c = cEnc + BH;
        la.d[1].h = hEnc + (size_t)(1 * 2 + (1 - p)) * BH;
        la.d[1].h2 = encOuts + (size_t)sb * EH + H;
        lstm_step_kernel<64><<<dim3(B / 64, H / 32, 2), 256>>>(la);
    }
    // final hidden states are at ping = S & 1 = 0
    const float* hF  = hEnc + (size_t)(0 * 2 + 0) * BH;
    const float* hBk = hEnc + (size_t)(1 * 2 + 0) * BH;

    // ---- h0 = tanh([h_f, h_b] @ enc_fc_W^T + enc_fc_b) -> hDec ping 0 ---------
    gemm_kernel<32, 64><<<dim3(B / 32, H / 64), 128>>>(
        hF, H, H, hBk, H, H, nullptr, 0, 0,
        enc_fc_W, EH, enc_fc_b, nullptr, 0, 1, hDec, H);

    // ---- encProj = enc_outs @ attn_W[:,256:768]^T + attn_b --------------------
    gemm_kernel<64, 64><<<dim3(B * S / 64, H / 64), 256>>>(
        encOuts, EH, EH, nullptr, 0, 0, nullptr, 0, 0,
        attn_W + H, H + EH, attn_b, nullptr, 0, 0, encProj, H);

    // ---- qp for t=0: h0 @ attn_W[:,0:256]^T -----------------------------------
    gemm_kernel<32, 64><<<dim3(B / 32, H / 64), 128>>>(
        hDec, H, H, nullptr, 0, 0, nullptr, 0, 0,
        attn_W, H + EH, nullptr, nullptr, 0, 0, qp, H);

    // ---- decoder loop ---------------------------------------------------------
    for (int t = 0; t < T; t++) {
        int p = t & 1, pn = (t + 1) & 1;
        float* hCur = hDec + (size_t)p * BH;
        float* hNew = hDec + (size_t)pn * BH;
        const float* eT = decEmb + (size_t)t * E;   // row stride T*E

        // attention -> ctx
        attn_kernel<<<B, 128>>>(src, qp, encProj, encOuts, attn_v, ctx);

        // LSTM step: gates = e@Wih[:,0:192]^T + ctx@Wih[:,192:704]^T + h@Whh^T + b
        LstmArgs2 la;
        la.d[0].A0 = eT;   la.d[0].ldA0 = T * E; la.d[0].K0 = E;
        la.d[0].A1 = ctx;  la.d[0].ldA1 = EH;    la.d[0].K1 = EH;
        la.d[0].A2 = hCur; la.d[0].ldA2 = H;     la.d[0].K2 = H;
        la.d[0].W0 = dec_Wih;     la.d[0].ldW0 = E + EH;
        la.d[0].W1 = dec_Wih + E; la.d[0].ldW1 = E + EH;
        la.d[0].W2 = dec_Whh;     la.d[0].ldW2 = H;
        la.d[0].G = nullptr; la.d[0].ldG = 0;
        la.d[0].bias = dec_b;
        la.d[0].c = cDec;
        la.d[0].h = hNew;
        la.d[0].h2 = nullptr; la.d[0].ldH2 = 0;
        la.d[1] = la.d[0];
        lstm_step_kernel<32><<<dim3(B / 32, H / 32, 1), 128>>>(la);

        // output: pred = [hNew | ctx | e] @ out_W^T + out_b
        gemm_kernel<32, 64><<<dim3(B / 32, V / 64), 128>>>(
            hNew, H, H, ctx, EH, EH, eT, T * E, E,
            out_W, H + EH + E, out_b, nullptr, 0, 0, out + (size_t)t * V, T * V);

        // qp for next step (uses hNew)
        if (t + 1 < T) {
            gemm_kernel<32, 64><<<dim3(B / 32, H / 64), 128>>>(
                hNew, H, H, nullptr, 0, 0, nullptr, 0, 0,
                attn_W, H + EH, nullptr, nullptr, 0, 0, qp, H);
        }
    }
}

// round 3
// speedup vs baseline: 1.0114x; 1.0114x over previous
#include <cuda_runtime.h>
#include <math.h>

// ---------------------------------------------------------------------------
// Problem constants
// ---------------------------------------------------------------------------
constexpr int B  = 512;
constexpr int S  = 64;
constexpr int T  = 120;
constexpr int E  = 192;
constexpr int H  = 256;
constexpr int EH = 512;   // 2H
constexpr int V  = 512;   // OUT_V
constexpr int G4 = 1024;  // 4H

#define DINL __device__ __forceinline__

// ---------------------------------------------------------------------------
// Scratch (static device globals -- allocation-free at launch time)
// ---------------------------------------------------------------------------
__device__ float g_Gin[(size_t)2 * B * S * G4];   // enc input gates (f, b), bias folded
__device__ float g_decEmb[(size_t)B * T * E];     // gathered teacher-forced dec embeddings
__device__ float g_encOuts[(size_t)B * S * EH];   // encoder outputs [b][s][2H]
__device__ float g_encProj[(size_t)B * S * H];    // enc_outs @ attn_We^T + attn_b
__device__ float g_hEnc[2 * 2 * B * H];           // [dir][ping][B][H]
__device__ float g_cEnc[2 * B * H];               // [dir][B][H]
__device__ float g_hDec[2 * B * H];               // [ping][B][H]
__device__ float g_cDec[B * H];
__device__ float g_ctx[B * EH];
__device__ float g_qp[B * H];                     // h @ attn_Wh^T

DINL float sigmoidf_(float x) { return 1.0f / (1.0f + expf(-x)); }

// ---------------------------------------------------------------------------
// zero fill
// ---------------------------------------------------------------------------
__global__ void zero_kernel(float* p, int n) {
    for (int i = blockIdx.x * blockDim.x + threadIdx.x; i < n; i += gridDim.x * blockDim.x)
        p[i] = 0.0f;
}

// ---------------------------------------------------------------------------
// Gather teacher-forced decoder embeddings: decEmb[b*T+t] = dec_emb[tok(b,t)]
// tok = (t==0) ? SOS(=1) : trg[b*T + t - 1]
// ---------------------------------------------------------------------------
__global__ __launch_bounds__(192) void dec_embed_gather_kernel(
    const int* __restrict__ trg,
    const float* __restrict__ dec_emb,
    float* __restrict__ decEmb)
{
    const int m = blockIdx.x;           // 0 .. B*T-1
    const int t = m % T;
    const int tok = (t == 0) ? 1 : trg[m - 1];
    decEmb[(size_t)m * E + threadIdx.x] = dec_emb[(size_t)tok * E + threadIdx.x];
}

// ---------------------------------------------------------------------------
// Embedding-gathered GEMM:  C[m][n] = sum_k emb[toks[m]][k] * W[n][k]  + bias[n]
// K = 192 fixed (encoder src path).
// ---------------------------------------------------------------------------
__global__ __launch_bounds__(256) void embed_gemm_kernel(
    const int* __restrict__ toks,
    const float* __restrict__ emb,
    const float* __restrict__ W, int ldW,
    const float* __restrict__ bias,
    float* __restrict__ C, int ldC)
{
    __shared__ float As[64][33];
    __shared__ float Bs[64][33];
    __shared__ int   stok[64];

    const int tid = threadIdx.x;
    const int m0 = blockIdx.x * 64;
    const int n0 = blockIdx.y * 64;
    const int ty = tid / 16, tx = tid % 16;

    if (tid < 64) stok[tid] = toks[m0 + tid];
    __syncthreads();

    float acc[4][4] = {};

    for (int kc = 0; kc < E; kc += 32) {
        #pragma unroll
        for (int idx = tid; idx < 512; idx += 256) {
            int r = idx >> 3, c4 = idx & 7;
            float4 v = *(const float4*)(emb + (size_t)stok[r] * E + kc + c4 * 4);
            As[r][c4 * 4 + 0] = v.x; As[r][c4 * 4 + 1] = v.y;
            As[r][c4 * 4 + 2] = v.z; As[r][c4 * 4 + 3] = v.w;
        }
        #pragma unroll
        for (int idx = tid; idx < 512; idx += 256) {
            int r = idx >> 3, c4 = idx & 7;
            float4 v = *(const float4*)(W + (size_t)(n0 + r) * ldW + kc + c4 * 4);
            Bs[r][c4 * 4 + 0] = v.x; Bs[r][c4 * 4 + 1] = v.y;
            Bs[r][c4 * 4 + 2] = v.z; Bs[r][c4 * 4 + 3] = v.w;
        }
        __syncthreads();
        #pragma unroll
        for (int k = 0; k < 32; k++) {
            float a[4], b[4];
            #pragma unroll
            for (int i = 0; i < 4; i++) a[i] = As[ty * 4 + i][k];
            #pragma unroll
            for (int j = 0; j < 4; j++) b[j] = Bs[tx * 4 + j][k];
            #pragma unroll
            for (int i = 0; i < 4; i++)
                #pragma unroll
                for (int j = 0; j < 4; j++) acc[i][j] += a[i] * b[j];
        }
        __syncthreads();
    }

    #pragma unroll
    for (int i = 0; i < 4; i++)
        #pragma unroll
        for (int j = 0; j < 4; j++) {
            int m = m0 + ty * 4 + i, n = n0 + tx * 4 + j;
            C[(size_t)m * ldC + n] = acc[i][j] + bias[n];
        }
}

// ---------------------------------------------------------------------------
// Generic fp32 GEMM:  C = act( [A0|A1|A2] @ W^T + bias + Cadd )
// A split into up to three K-segments (row-major, K-contiguous).
// W row-major [N][ldW], K-contiguous across all segments.
// act: 0 = none, 1 = tanh
// ---------------------------------------------------------------------------
template <int BM, int BN>
__global__ __launch_bounds__((BM / 4) * (BN / 4)) void gemm_kernel(
    const float* __restrict__ A0, int ldA0, int K0,
    const float* __restrict__ A1, int ldA1, int K1,
    const float* __restrict__ A2, int ldA2, int K2,
    const float* __restrict__ W, int ldW,
    const float* __restrict__ bias,
    const float* __restrict__ Cadd, int ldAdd,
    int act,
    float* __restrict__ C, int ldC)
{
    constexpr int NT = (BM / 4) * (BN / 4);
    __shared__ float As[BM][33];
    __shared__ float Bs[BN][33];

    const int tid = threadIdx.x;
    const int m0 = blockIdx.x * BM;
    const int n0 = blockIdx.y * BN;
    const int ty = tid / (BN / 4), tx = tid % (BN / 4);

    float acc[4][4] = {};
    const int K = K0 + K1 + K2;

    for (int kc = 0; kc < K; kc += 32) {
        const float* Ab; int ldA, kk0;
        if (kc < K0)            { Ab = A0; ldA = ldA0; kk0 = kc; }
        else if (kc < K0 + K1)  { Ab = A1; ldA = ldA1; kk0 = kc - K0; }
        else                    { Ab = A2; ldA = ldA2; kk0 = kc - K0 - K1; }

        #pragma unroll
        for (int idx = tid; idx < BM * 8; idx += NT) {
            int r = idx >> 3, c4 = idx & 7;
            float4 v = *(const float4*)(Ab + (size_t)(m0 + r) * ldA + kk0 + c4 * 4);
            As[r][c4 * 4 + 0] = v.x; As[r][c4 * 4 + 1] = v.y;
            As[r][c4 * 4 + 2] = v.z; As[r][c4 * 4 + 3] = v.w;
        }
        #pragma unroll
        for (int idx = tid; idx < BN * 8; idx += NT) {
            int r = idx >> 3, c4 = idx & 7;
            float4 v = *(const float4*)(W + (size_t)(n0 + r) * ldW + kc + c4 * 4);
            Bs[r][c4 * 4 + 0] = v.x; Bs[r][c4 * 4 + 1] = v.y;
            Bs[r][c4 * 4 + 2] = v.z; Bs[r][c4 * 4 + 3] = v.w;
        }
        __syncthreads();
        #pragma unroll
        for (int k = 0; k < 32; k++) {
            float a[4], b[4];
            #pragma unroll
            for (int i = 0; i < 4; i++) a[i] = As[ty * 4 + i][k];
            #pragma unroll
            for (int j = 0; j < 4; j++) b[j] = Bs[tx * 4 + j][k];
            #pragma unroll
            for (int i = 0; i < 4; i++)
                #pragma unroll
                for (int j = 0; j < 4; j++) acc[i][j] += a[i] * b[j];
        }
        __syncthreads();
    }

    #pragma unroll
    for (int i = 0; i < 4; i++)
        #pragma unroll
        for (int j = 0; j < 4; j++) {
            int m = m0 + ty * 4 + i, n = n0 + tx * 4 + j;
            float vv = acc[i][j];
            if (bias) vv += bias[n];
            if (Cadd) vv += Cadd[(size_t)m * ldAdd + n];
            if (act == 1) vv = tanhf(vv);
            C[(size_t)m * ldC + n] = vv;
        }
}

// ---------------------------------------------------------------------------
// Fused LSTM step:
//   gates[m][g*256+j] = Gadd[m][g*256+j](opt) + bias[g*256+j](opt)
//                     + sum_k [A0|A1|A2][m][k] * [Wseg][g*256+j][k]
//   c' = sig(f)*c + sig(i)*tanh(g);  h' = sig(o)*tanh(c')
// Block computes BM rows x 32 j-columns x all 4 gates.
// blockIdx.z selects the direction parameter set (encoder fwd/bwd fused).
// ---------------------------------------------------------------------------
struct LstmDirArgs {
    const float* A0; int ldA0, K0;
    const float* A1; int ldA1, K1;
    const float* A2; int ldA2, K2;
    const float* W0; int ldW0;   // covers K-range [0, K0)
    const float* W1; int ldW1;   // covers K-range [K0, K0+K1)
    const float* W2; int ldW2;   // covers K-range [K0+K1, K)
    const float* G;  int ldG;    // optional precomputed gate term (may be null)
    const float* bias;           // optional [4H] bias (may be null)
    float* c;                    // [M][256] in/out
    float* h;                    // [M][256] out (ping buffer)
    float* h2; int ldH2;         // optional second h write (enc_outs slice)
};
struct LstmArgs2 { LstmDirArgs d[2]; };

template <int BM>
__global__ __launch_bounds__((BM / 4) * 16) void lstm_step_kernel(LstmArgs2 aa)
{
    const LstmDirArgs a = aa.d[blockIdx.z];
    constexpr int NT = (BM / 4) * 16;
    __shared__ float As[BM][33];
    __shared__ float Ws[4][32][33];

    const int tid = threadIdx.x;
    const int m0 = blockIdx.x * BM;
    const int j0 = blockIdx.y * 32;
    const int ty = tid / 16, tx = tid % 16;

    float acc[4][2][4] = {};   // [mi][jj][gate]
    const int K = a.K0 + a.K1 + a.K2;

    for (int kc = 0; kc < K; kc += 32) {
        const float* Ab; int ldA, kk0;
        const float* Wb; int ldWb;
        if (kc < a.K0) {
            Ab = a.A0; ldA = a.ldA0; kk0 = kc;
            Wb = a.W0; ldWb = a.ldW0;
        } else if (kc < a.K0 + a.K1) {
            Ab = a.A1; ldA = a.ldA1; kk0 = kc - a.K0;
            Wb = a.W1; ldWb = a.ldW1;
        } else {
            Ab = a.A2; ldA = a.ldA2; kk0 = kc - a.K0 - a.K1;
            Wb = a.W2; ldWb = a.ldW2;
        }
        #pragma unroll
        for (int idx = tid; idx < BM * 8; idx += NT) {
            int r = idx >> 3, c4 = idx & 7;
            float4 v = *(const float4*)(Ab + (size_t)(m0 + r) * ldA + kk0 + c4 * 4);
            As[r][c4 * 4 + 0] = v.x; As[r][c4 * 4 + 1] = v.y;
            As[r][c4 * 4 + 2] = v.z; As[r][c4 * 4 + 3] = v.w;
        }
        #pragma unroll
        for (int idx = tid; idx < 1024; idx += NT) {
            int g = idx >> 8, rem = idx & 255, j = rem >> 3, c4 = rem & 7;
            int n = g * 256 + j0 + j;
            float4 v = *(const float4*)(Wb + (size_t)n * ldWb + kk0 + c4 * 4);
            Ws[g][j][c4 * 4 + 0] = v.x; Ws[g][j][c4 * 4 + 1] = v.y;
            Ws[g][j][c4 * 4 + 2] = v.z; Ws[g][j][c4 * 4 + 3] = v.w;
        }
        __syncthreads();
        #pragma unroll
        for (int k = 0; k < 32; k++) {
            float av[4];
            #pragma unroll
            for (int mi = 0; mi < 4; mi++) av[mi] = As[ty * 4 + mi][k];
            #pragma unroll
            for (int jj = 0; jj < 2; jj++) {
                #pragma unroll
                for (int g = 0; g < 4; g++) {
                    float w = Ws[g][tx * 2 + jj][k];
                    #pragma unroll
                    for (int mi = 0; mi < 4; mi++) acc[mi][jj][g] += av[mi] * w;
                }
            }
        }
        __syncthreads();
    }

    #pragma unroll
    for (int mi = 0; mi < 4; mi++) {
        #pragma unroll
        for (int jj = 0; jj < 2; jj++) {
            int m = m0 + ty * 4 + mi;
            int j = j0 + tx * 2 + jj;
            float gi = acc[mi][jj][0];
            float gf = acc[mi][jj][1];
            float gg = acc[mi][jj][2];
            float go = acc[mi][jj][3];
            if (a.G) {
                const float* gr = a.G + (size_t)m * a.ldG;
                gi += gr[j]; gf += gr[256 + j]; gg += gr[512 + j]; go += gr[768 + j];
            }
            if (a.bias) {
                gi += a.bias[j];       gf += a.bias[256 + j];
                gg += a.bias[512 + j]; go += a.bias[768 + j];
            }
            float cold = a.c[m * 256 + j];
            float cn = sigmoidf_(gf) * cold + sigmoidf_(gi) * tanhf(gg);
            float hn = sigmoidf_(go) * tanhf(cn);
            a.c[m * 256 + j] = cn;
            a.h[m * 256 + j] = hn;
            if (a.h2) a.h2[(size_t)m * a.ldH2 + j] = hn;
        }
    }
}

// ---------------------------------------------------------------------------
// Attention step (per-batch-row block, 128 threads):
//   score[s] = sum_j v[j] * tanh(qp[b][j] + encProj[b][s][j])    (masked)
//   aw = softmax(score);  ctx[b] = sum_s aw[s] * encOuts[b][s][:]
// ---------------------------------------------------------------------------
__global__ __launch_bounds__(128) void attn_kernel(
    const int* __restrict__ src,
    const float* __restrict__ qp,
    const float* __restrict__ encProj,
    const float* __restrict__ encOuts,
    const float* __restrict__ v,
    float* __restrict__ ctx)
{
    const int b = blockIdx.x;
    const int tid = threadIdx.x;
    __shared__ float qpv[256];
    __shared__ float vv[256];
    __shared__ float sc[64];

    qpv[tid]       = qp[b * 256 + tid];
    qpv[tid + 128] = qp[b * 256 + 128 + tid];
    vv[tid]        = v[tid];
    vv[tid + 128]  = v[tid + 128];
    __syncthreads();

    const int w = tid >> 5, lane = tid & 31;
    #pragma unroll 4
    for (int i = 0; i < 16; i++) {
        int s = w * 16 + i;
        const float* ep = encProj + (size_t)(b * 64 + s) * 256;
        float sum = 0.0f;
        #pragma unroll
        for (int r = 0; r < 8; r++) {
            int j = lane + r * 32;
            sum += tanhf(qpv[j] + ep[j]) * vv[j];
        }
        #pragma unroll
        for (int off = 16; off > 0; off >>= 1)
            sum += __shfl_xor_sync(0xffffffffu, sum, off);
        if (lane == 0)
            sc[s] = (src[b * 64 + s] != 0) ? sum : -1e9f;
    }
    __syncthreads();

    if (tid < 32) {
        float a = sc[tid], b2 = sc[tid + 32];
        float mx = fmaxf(a, b2);
        #pragma unroll
        for (int off = 16; off > 0; off >>= 1)
            mx = fmaxf(mx, __shfl_xor_sync(0xffffffffu, mx, off));
        float ea = expf(a - mx), eb = expf(b2 - mx);
        float sm = ea + eb;
        #pragma unroll
        for (int off = 16; off > 0; off >>= 1)
            sm += __shfl_xor_sync(0xffffffffu, sm, off);
        float inv = 1.0f / sm;
        sc[tid] = ea * inv;
        sc[tid + 32] = eb * inv;
    }
    __syncthreads();

    const int kk = tid * 4;
    float4 accv = make_float4(0.f, 0.f, 0.f, 0.f);
    #pragma unroll 4
    for (int s = 0; s < 64; s++) {
        float wgt = sc[s];
        float4 e = *(const float4*)(encOuts + (size_t)(b * 64 + s) * 512 + kk);
        accv.x += wgt * e.x; accv.y += wgt * e.y;
        accv.z += wgt * e.z; accv.w += wgt * e.w;
    }
    *(float4*)(ctx + (size_t)b * 512 + kk) = accv;
}

// ---------------------------------------------------------------------------
// Host orchestration
// ---------------------------------------------------------------------------
extern "C" void kernel_launch(void* const* d_in, const int* in_sizes, int n_in,
                              void* d_out, int out_size)
{
    const int*   src       = (const int*)d_in[0];
    // d_in[1] = src_len (unused: all full-length; mask comes from src != 0)
    const int*   trg       = (const int*)d_in[2];
    const float* enc_emb   = (const float*)d_in[3];
    const float* enc_Wih_f = (const float*)d_in[4];
    const float* enc_Whh_f = (const float*)d_in[5];
    const float* enc_b_f   = (const float*)d_in[6];
    const float* enc_Wih_b = (const float*)d_in[7];
    const float* enc_Whh_b = (const float*)d_in[8];
    const float* enc_b_b   = (const float*)d_in[9];
    const float* enc_fc_W  = (const float*)d_in[10];
    const float* enc_fc_b  = (const float*)d_in[11];
    const float* dec_emb   = (const float*)d_in[12];
    const float* dec_Wih   = (const float*)d_in[13];
    const float* dec_Whh   = (const float*)d_in[14];
    const float* dec_b     = (const float*)d_in[15];
    const float* attn_W    = (const float*)d_in[16];
    const float* attn_b    = (const float*)d_in[17];
    const float* attn_v    = (const float*)d_in[18];
    const float* out_W     = (const float*)d_in[19];
    const float* out_b     = (const float*)d_in[20];
    float* out = (float*)d_out;

    float *Gin, *decEmb, *encOuts, *encProj, *hEnc, *cEnc, *hDec, *cDec, *ctx, *qp;
    cudaGetSymbolAddress((void**)&Gin,     g_Gin);
    cudaGetSymbolAddress((void**)&decEmb,  g_decEmb);
    cudaGetSymbolAddress((void**)&encOuts, g_encOuts);
    cudaGetSymbolAddress((void**)&encProj, g_encProj);
    cudaGetSymbolAddress((void**)&hEnc,    g_hEnc);
    cudaGetSymbolAddress((void**)&cEnc,    g_cEnc);
    cudaGetSymbolAddress((void**)&hDec,    g_hDec);
    cudaGetSymbolAddress((void**)&cDec,    g_cDec);
    cudaGetSymbolAddress((void**)&ctx,     g_ctx);
    cudaGetSymbolAddress((void**)&qp,      g_qp);

    const size_t GINSZ = (size_t)B * S * G4;      // per-direction Gin stride
    const int    BH    = B * H;

    // ---- zero recurrent state -------------------------------------------------
    zero_kernel<<<256, 256>>>(hEnc, 4 * BH);
    zero_kernel<<<256, 256>>>(cEnc, 2 * BH);
    zero_kernel<<<128, 256>>>(cDec, BH);

    // ---- precompute: encoder input gates + decoder embedding gather -----------
    embed_gemm_kernel<<<dim3(B * S / 64, G4 / 64), 256>>>(
        src, enc_emb, enc_Wih_f, E, enc_b_f, Gin, G4);
    embed_gemm_kernel<<<dim3(B * S / 64, G4 / 64), 256>>>(
        src, enc_emb, enc_Wih_b, E, enc_b_b, Gin + GINSZ, G4);
    dec_embed_gather_kernel<<<B * T, 192>>>(trg, dec_emb, decEmb);

    // ---- encoder recurrence (fwd + bwd fused via blockIdx.z) ------------------
    for (int t = 0; t < S; t++) {
        int p = t & 1;
        LstmArgs2 la;
        // forward
        la.d[0].A0 = hEnc + (size_t)(0 * 2 + p) * BH; la.d[0].ldA0 = H; la.d[0].K0 = H;
        la.d[0].A1 = nullptr; la.d[0].ldA1 = 0; la.d[0].K1 = 0;
        la.d[0].A2 = nullptr; la.d[0].ldA2 = 0; la.d[0].K2 = 0;
        la.d[0].W0 = enc_Whh_f; la.d[0].ldW0 = H;
        la.d[0].W1 = nullptr;   la.d[0].ldW1 = 0;
        la.d[0].W2 = nullptr;   la.d[0].ldW2 = 0;
        la.d[0].G = Gin + (size_t)t * G4; la.d[0].ldG = S * G4;
        la.d[0].bias = nullptr;
        la.d[0].c = cEnc;
        la.d[0].h = hEnc + (size_t)(0 * 2 + (1 - p)) * BH;
        la.d[0].h2 = encOuts + (size_t)t * EH;   // enc_outs[:, t, 0:256]
        la.d[0].ldH2 = S * EH;
        // backward (input at s = S-1-t, output slot s = S-1-t, cols 256:512)
        int sb = S - 1 - t;
        la.d[1] = la.d[0];
        la.d[1].A0 = hEnc + (size_t)(1 * 2 + p) * BH;
        la.d[1].W0 = enc_Whh_b;
        la.d[1].G = Gin + GINSZ + (size_t)sb * G4;
        la.d[1].c = cEnc + BH;
        la.d[1].h = hEnc + (size_t)(1 * 2 + (1 - p)) * BH;
        la.d[1].h2 = encOuts + (size_t)sb * EH + H;
        lstm_step_kernel<64><<<dim3(B / 64, H / 32, 2), 256>>>(la);
    }
    // final hidden states are at ping = S & 1 = 0
    const float* hF  = hEnc + (size_t)(0 * 2 + 0) * BH;
    const float* hBk = hEnc + (size_t)(1 * 2 + 0) * BH;

    // ---- h0 = tanh([h_f, h_b] @ enc_fc_W^T + enc_fc_b) -> hDec ping 0 ---------
    gemm_kernel<32, 64><<<dim3(B / 32, H / 64), 128>>>(
        hF, H, H, hBk, H, H, nullptr, 0, 0,
        enc_fc_W, EH, enc_fc_b, nullptr, 0, 1, hDec, H);

    // ---- encProj = enc_outs @ attn_W[:,256:768]^T + attn_b --------------------
    gemm_kernel<64, 64><<<dim3(B * S / 64, H / 64), 256>>>(
        encOuts, EH, EH, nullptr, 0, 0, nullptr, 0, 0,
        attn_W + H, H + EH, attn_b, nullptr, 0, 0, encProj, H);

    // ---- qp for t=0: h0 @ attn_W[:,0:256]^T -----------------------------------
    gemm_kernel<32, 64><<<dim3(B / 32, H / 64), 128>>>(
        hDec, H, H, nullptr, 0, 0, nullptr, 0, 0,
        attn_W, H + EH, nullptr, nullptr, 0, 0, qp, H);

    // ---- decoder loop ---------------------------------------------------------
    for (int t = 0; t < T; t++) {
        int p = t & 1, pn = (t + 1) & 1;
        float* hCur = hDec + (size_t)p * BH;
        float* hNew = hDec + (size_t)pn * BH;
        const float* eT = decEmb + (size_t)t * E;   // row stride T*E

        // attention -> ctx
        attn_kernel<<<B, 128>>>(src, qp, encProj, encOuts, attn_v, ctx);

        // LSTM step: gates = e@Wih[:,0:192]^T + ctx@Wih[:,192:704]^T + h@Whh^T + b
        LstmArgs2 la;
        la.d[0].A0 = eT;   la.d[0].ldA0 = T * E; la.d[0].K0 = E;
        la.d[0].A1 = ctx;  la.d[0].ldA1 = EH;    la.d[0].K1 = EH;
        la.d[0].A2 = hCur; la.d[0].ldA2 = H;     la.d[0].K2 = H;
        la.d[0].W0 = dec_Wih;     la.d[0].ldW0 = E + EH;
        la.d[0].W1 = dec_Wih + E; la.d[0].ldW1 = E + EH;
        la.d[0].W2 = dec_Whh;     la.d[0].ldW2 = H;
        la.d[0].G = nullptr; la.d[0].ldG = 0;
        la.d[0].bias = dec_b;
        la.d[0].c = cDec;
        la.d[0].h = hNew;
        la.d[0].h2 = nullptr; la.d[0].ldH2 = 0;
        la.d[1] = la.d[0];
        lstm_step_kernel<32><<<dim3(B / 32, H / 32, 1), 128>>>(la);

        // output: pred = [hNew | ctx | e] @ out_W^T + out_b
        gemm_kernel<32, 64><<<dim3(B / 32, V / 64), 128>>>(
            hNew, H, H, ctx, EH, EH, eT, T * E, E,
            out_W, H + EH + E, out_b, nullptr, 0, 0, out + (size_t)t * V, T * V);

        // qp for next step (uses hNew)
        if (t + 1 < T) {
            gemm_kernel<32, 64><<<dim3(B / 32, H / 64), 128>>>(
                hNew, H, H, nullptr, 0, 0, nullptr, 0, 0,
                attn_W, H + EH, nullptr, nullptr, 0, 0, qp, H);
        }
    }
}

// round 4
// speedup vs baseline: 1.0116x; 1.0001x over previous
#include <cuda_runtime.h>
#include <math.h>

// ---------------------------------------------------------------------------
// Problem constants
// ---------------------------------------------------------------------------
constexpr int B  = 512;
constexpr int S  = 64;
constexpr int T  = 120;
constexpr int E  = 192;
constexpr int H  = 256;
constexpr int EH = 512;   // 2H
constexpr int V  = 512;   // OUT_V
constexpr int G4 = 1024;  // 4H

#define DINL __device__ __forceinline__

// ---------------------------------------------------------------------------
// Scratch (static device globals -- allocation-free at launch time)
// ---------------------------------------------------------------------------
__device__ float g_Gin[(size_t)2 * B * S * G4];   // enc input gates (f, b), bias folded
__device__ float g_decEmb[(size_t)B * T * E];     // gathered teacher-forced dec embeddings
__device__ float g_encOuts[(size_t)B * S * EH];   // encoder outputs [b][s][2H]
__device__ float g_encProj[(size_t)B * S * H];    // enc_outs @ attn_We^T + attn_b
__device__ float g_hEnc[2 * 2 * B * H];           // [dir][ping][B][H]
__device__ float g_cEnc[2 * B * H];               // [dir][B][H]
__device__ float g_hDec[2 * B * H];               // [ping][B][H]
__device__ float g_cDec[B * H];
__device__ float g_ctx[B * EH];
__device__ float g_qp[B * H];                     // h @ attn_Wh^T

DINL float sigmoidf_(float x) { return 1.0f / (1.0f + expf(-x)); }

// ---------------------------------------------------------------------------
// zero fill
// ---------------------------------------------------------------------------
__global__ void zero_kernel(float* p, int n) {
    for (int i = blockIdx.x * blockDim.x + threadIdx.x; i < n; i += gridDim.x * blockDim.x)
        p[i] = 0.0f;
}

// ---------------------------------------------------------------------------
// Gather teacher-forced decoder embeddings: decEmb[b*T+t] = dec_emb[tok(b,t)]
// tok = (t==0) ? SOS(=1) : trg[b*T + t - 1]
// ---------------------------------------------------------------------------
__global__ __launch_bounds__(192) void dec_embed_gather_kernel(
    const int* __restrict__ trg,
    const float* __restrict__ dec_emb,
    float* __restrict__ decEmb)
{
    const int m = blockIdx.x;           // 0 .. B*T-1
    const int t = m % T;
    const int tok = (t == 0) ? 1 : trg[m - 1];
    decEmb[(size_t)m * E + threadIdx.x] = dec_emb[(size_t)tok * E + threadIdx.x];
}

// ---------------------------------------------------------------------------
// Embedding-gathered GEMM:  C[m][n] = sum_k emb[toks[m]][k] * W[n][k]  + bias[n]
// K = 192 fixed (encoder src path).
// ---------------------------------------------------------------------------
__global__ __launch_bounds__(256) void embed_gemm_kernel(
    const int* __restrict__ toks,
    const float* __restrict__ emb,
    const float* __restrict__ W, int ldW,
    const float* __restrict__ bias,
    float* __restrict__ C, int ldC)
{
    __shared__ float As[64][33];
    __shared__ float Bs[64][33];
    __shared__ int   stok[64];

    const int tid = threadIdx.x;
    const int m0 = blockIdx.x * 64;
    const int n0 = blockIdx.y * 64;
    const int ty = tid / 16, tx = tid % 16;

    if (tid < 64) stok[tid] = toks[m0 + tid];
    __syncthreads();

    float acc[4][4] = {};

    for (int kc = 0; kc < E; kc += 32) {
        #pragma unroll
        for (int idx = tid; idx < 512; idx += 256) {
            int r = idx >> 3, c4 = idx & 7;
            float4 v = *(const float4*)(emb + (size_t)stok[r] * E + kc + c4 * 4);
            As[r][c4 * 4 + 0] = v.x; As[r][c4 * 4 + 1] = v.y;
            As[r][c4 * 4 + 2] = v.z; As[r][c4 * 4 + 3] = v.w;
        }
        #pragma unroll
        for (int idx = tid; idx < 512; idx += 256) {
            int r = idx >> 3, c4 = idx & 7;
            float4 v = *(const float4*)(W + (size_t)(n0 + r) * ldW + kc + c4 * 4);
            Bs[r][c4 * 4 + 0] = v.x; Bs[r][c4 * 4 + 1] = v.y;
            Bs[r][c4 * 4 + 2] = v.z; Bs[r][c4 * 4 + 3] = v.w;
        }
        __syncthreads();
        #pragma unroll
        for (int k = 0; k < 32; k++) {
            float a[4], b[4];
            #pragma unroll
            for (int i = 0; i < 4; i++) a[i] = As[ty * 4 + i][k];
            #pragma unroll
            for (int j = 0; j < 4; j++) b[j] = Bs[tx * 4 + j][k];
            #pragma unroll
            for (int i = 0; i < 4; i++)
                #pragma unroll
                for (int j = 0; j < 4; j++) acc[i][j] += a[i] * b[j];
        }
        __syncthreads();
    }

    #pragma unroll
    for (int i = 0; i < 4; i++)
        #pragma unroll
        for (int j = 0; j < 4; j++) {
            int m = m0 + ty * 4 + i, n = n0 + tx * 4 + j;
            C[(size_t)m * ldC + n] = acc[i][j] + bias[n];
        }
}

// ---------------------------------------------------------------------------
// Generic fp32 GEMM:  C = act( [A0|A1|A2] @ W^T + bias + Cadd )
// A split into up to three K-segments (row-major, K-contiguous).
// W row-major [N][ldW], K-contiguous across all segments.
// act: 0 = none, 1 = tanh
// ---------------------------------------------------------------------------
template <int BM, int BN>
__global__ __launch_bounds__((BM / 4) * (BN / 4)) void gemm_kernel(
    const float* __restrict__ A0, int ldA0, int K0,
    const float* __restrict__ A1, int ldA1, int K1,
    const float* __restrict__ A2, int ldA2, int K2,
    const float* __restrict__ W, int ldW,
    const float* __restrict__ bias,
    const float* __restrict__ Cadd, int ldAdd,
    int act,
    float* __restrict__ C, int ldC)
{
    constexpr int NT = (BM / 4) * (BN / 4);
    __shared__ float As[BM][33];
    __shared__ float Bs[BN][33];

    const int tid = threadIdx.x;
    const int m0 = blockIdx.x * BM;
    const int n0 = blockIdx.y * BN;
    const int ty = tid / (BN / 4), tx = tid % (BN / 4);

    float acc[4][4] = {};
    const int K = K0 + K1 + K2;

    for (int kc = 0; kc < K; kc += 32) {
        const float* Ab; int ldA, kk0;
        if (kc < K0)            { Ab = A0; ldA = ldA0; kk0 = kc; }
        else if (kc < K0 + K1)  { Ab = A1; ldA = ldA1; kk0 = kc - K0; }
        else                    { Ab = A2; ldA = ldA2; kk0 = kc - K0 - K1; }

        #pragma unroll
        for (int idx = tid; idx < BM * 8; idx += NT) {
            int r = idx >> 3, c4 = idx & 7;
            float4 v = *(const float4*)(Ab + (size_t)(m0 + r) * ldA + kk0 + c4 * 4);
            As[r][c4 * 4 + 0] = v.x; As[r][c4 * 4 + 1] = v.y;
            As[r][c4 * 4 + 2] = v.z; As[r][c4 * 4 + 3] = v.w;
        }
        #pragma unroll
        for (int idx = tid; idx < BN * 8; idx += NT) {
            int r = idx >> 3, c4 = idx & 7;
            float4 v = *(const float4*)(W + (size_t)(n0 + r) * ldW + kc + c4 * 4);
            Bs[r][c4 * 4 + 0] = v.x; Bs[r][c4 * 4 + 1] = v.y;
            Bs[r][c4 * 4 + 2] = v.z; Bs[r][c4 * 4 + 3] = v.w;
        }
        __syncthreads();
        #pragma unroll
        for (int k = 0; k < 32; k++) {
            float a[4], b[4];
            #pragma unroll
            for (int i = 0; i < 4; i++) a[i] = As[ty * 4 + i][k];
            #pragma unroll
            for (int j = 0; j < 4; j++) b[j] = Bs[tx * 4 + j][k];
            #pragma unroll
            for (int i = 0; i < 4; i++)
                #pragma unroll
                for (int j = 0; j < 4; j++) acc[i][j] += a[i] * b[j];
        }
        __syncthreads();
    }

    #pragma unroll
    for (int i = 0; i < 4; i++)
        #pragma unroll
        for (int j = 0; j < 4; j++) {
            int m = m0 + ty * 4 + i, n = n0 + tx * 4 + j;
            float vv = acc[i][j];
            if (bias) vv += bias[n];
            if (Cadd) vv += Cadd[(size_t)m * ldAdd + n];
            if (act == 1) vv = tanhf(vv);
            C[(size_t)m * ldC + n] = vv;
        }
}

// ---------------------------------------------------------------------------
// Fused LSTM step:
//   gates[m][g*256+j] = Gadd[m][g*256+j](opt) + bias[g*256+j](opt)
//                     + sum_k [A0|A1|A2][m][k] * [Wseg][g*256+j][k]
//   c' = sig(f)*c + sig(i)*tanh(g);  h' = sig(o)*tanh(c')
// Block computes BM rows x 32 j-columns x all 4 gates.
// blockIdx.z selects the direction parameter set (encoder fwd/bwd fused).
// ---------------------------------------------------------------------------
struct LstmDirArgs {
    const float* A0; int ldA0, K0;
    const float* A1; int ldA1, K1;
    const float* A2; int ldA2, K2;
    const float* W0; int ldW0;   // covers K-range [0, K0)
    const float* W1; int ldW1;   // covers K-range [K0, K0+K1)
    const float* W2; int ldW2;   // covers K-range [K0+K1, K)
    const float* G;  int ldG;    // optional precomputed gate term (may be null)
    const float* bias;           // optional [4H] bias (may be null)
    float* c;                    // [M][256] in/out
    float* h;                    // [M][256] out (ping buffer)
    float* h2; int ldH2;         // optional second h write (enc_outs slice)
};
struct LstmArgs2 { LstmDirArgs d[2]; };

template <int BM>
__global__ __launch_bounds__((BM / 4) * 16) void lstm_step_kernel(LstmArgs2 aa)
{
    const LstmDirArgs a = aa.d[blockIdx.z];
    constexpr int NT = (BM / 4) * 16;
    __shared__ float As[BM][33];
    __shared__ float Ws[4][32][33];

    const int tid = threadIdx.x;
    const int m0 = blockIdx.x * BM;
    const int j0 = blockIdx.y * 32;
    const int ty = tid / 16, tx = tid % 16;

    float acc[4][2][4] = {};   // [mi][jj][gate]
    const int K = a.K0 + a.K1 + a.K2;

    for (int kc = 0; kc < K; kc += 32) {
        const float* Ab; int ldA, kk0;
        const float* Wb; int ldWb;
        if (kc < a.K0) {
            Ab = a.A0; ldA = a.ldA0; kk0 = kc;
            Wb = a.W0; ldWb = a.ldW0;
        } else if (kc < a.K0 + a.K1) {
            Ab = a.A1; ldA = a.ldA1; kk0 = kc - a.K0;
            Wb = a.W1; ldWb = a.ldW1;
        } else {
            Ab = a.A2; ldA = a.ldA2; kk0 = kc - a.K0 - a.K1;
            Wb = a.W2; ldWb = a.ldW2;
        }
        #pragma unroll
        for (int idx = tid; idx < BM * 8; idx += NT) {
            int r = idx >> 3, c4 = idx & 7;
            float4 v = *(const float4*)(Ab + (size_t)(m0 + r) * ldA + kk0 + c4 * 4);
            As[r][c4 * 4 + 0] = v.x; As[r][c4 * 4 + 1] = v.y;
            As[r][c4 * 4 + 2] = v.z; As[r][c4 * 4 + 3] = v.w;
        }
        #pragma unroll
        for (int idx = tid; idx < 1024; idx += NT) {
            int g = idx >> 8, rem = idx & 255, j = rem >> 3, c4 = rem & 7;
            int n = g * 256 + j0 + j;
            float4 v = *(const float4*)(Wb + (size_t)n * ldWb + kk0 + c4 * 4);
            Ws[g][j][c4 * 4 + 0] = v.x; Ws[g][j][c4 * 4 + 1] = v.y;
            Ws[g][j][c4 * 4 + 2] = v.z; Ws[g][j][c4 * 4 + 3] = v.w;
        }
        __syncthreads();
        #pragma unroll
        for (int k = 0; k < 32; k++) {
            float av[4];
            #pragma unroll
            for (int mi = 0; mi < 4; mi++) av[mi] = As[ty * 4 + mi][k];
            #pragma unroll
            for (int jj = 0; jj < 2; jj++) {
                #pragma unroll
                for (int g = 0; g < 4; g++) {
                    float w = Ws[g][tx * 2 + jj][k];
                    #pragma unroll
                    for (int mi = 0; mi < 4; mi++) acc[mi][jj][g] += av[mi] * w;
                }
            }
        }
        __syncthreads();
    }

    #pragma unroll
    for (int mi = 0; mi < 4; mi++) {
        #pragma unroll
        for (int jj = 0; jj < 2; jj++) {
            int m = m0 + ty * 4 + mi;
            int j = j0 + tx * 2 + jj;
            float gi = acc[mi][jj][0];
            float gf = acc[mi][jj][1];
            float gg = acc[mi][jj][2];
            float go = acc[mi][jj][3];
            if (a.G) {
                const float* gr = a.G + (size_t)m * a.ldG;
                gi += gr[j]; gf += gr[256 + j]; gg += gr[512 + j]; go += gr[768 + j];
            }
            if (a.bias) {
                gi += a.bias[j];       gf += a.bias[256 + j];
                gg += a.bias[512 + j]; go += a.bias[768 + j];
            }
            float cold = a.c[m * 256 + j];
            float cn = sigmoidf_(gf) * cold + sigmoidf_(gi) * tanhf(gg);
            float hn = sigmoidf_(go) * tanhf(cn);
            a.c[m * 256 + j] = cn;
            a.h[m * 256 + j] = hn;
            if (a.h2) a.h2[(size_t)m * a.ldH2 + j] = hn;
        }
    }
}

// ---------------------------------------------------------------------------
// Attention step (per-batch-row block, 128 threads):
//   score[s] = sum_j v[j] * tanh(qp[b][j] + encProj[b][s][j])    (masked)
//   aw = softmax(score);  ctx[b] = sum_s aw[s] * encOuts[b][s][:]
// ---------------------------------------------------------------------------
__global__ __launch_bounds__(128) void attn_kernel(
    const int* __restrict__ src,
    const float* __restrict__ qp,
    const float* __restrict__ encProj,
    const float* __restrict__ encOuts,
    const float* __restrict__ v,
    float* __restrict__ ctx)
{
    const int b = blockIdx.x;
    const int tid = threadIdx.x;
    __shared__ float qpv[256];
    __shared__ float vv[256];
    __shared__ float sc[64];

    qpv[tid]       = qp[b * 256 + tid];
    qpv[tid + 128] = qp[b * 256 + 128 + tid];
    vv[tid]        = v[tid];
    vv[tid + 128]  = v[tid + 128];
    __syncthreads();

    const int w = tid >> 5, lane = tid & 31;
    #pragma unroll 4
    for (int i = 0; i < 16; i++) {
        int s = w * 16 + i;
        const float* ep = encProj + (size_t)(b * 64 + s) * 256;
        float sum = 0.0f;
        #pragma unroll
        for (int r = 0; r < 8; r++) {
            int j = lane + r * 32;
            sum += tanhf(qpv[j] + ep[j]) * vv[j];
        }
        #pragma unroll
        for (int off = 16; off > 0; off >>= 1)
            sum += __shfl_xor_sync(0xffffffffu, sum, off);
        if (lane == 0)
            sc[s] = (src[b * 64 + s] != 0) ? sum : -1e9f;
    }
    __syncthreads();

    if (tid < 32) {
        float a = sc[tid], b2 = sc[tid + 32];
        float mx = fmaxf(a, b2);
        #pragma unroll
        for (int off = 16; off > 0; off >>= 1)
            mx = fmaxf(mx, __shfl_xor_sync(0xffffffffu, mx, off));
        float ea = expf(a - mx), eb = expf(b2 - mx);
        float sm = ea + eb;
        #pragma unroll
        for (int off = 16; off > 0; off >>= 1)
            sm += __shfl_xor_sync(0xffffffffu, sm, off);
        float inv = 1.0f / sm;
        sc[tid] = ea * inv;
        sc[tid + 32] = eb * inv;
    }
    __syncthreads();

    const int kk = tid * 4;
    float4 accv = make_float4(0.f, 0.f, 0.f, 0.f);
    #pragma unroll 4
    for (int s = 0; s < 64; s++) {
        float wgt = sc[s];
        float4 e = *(const float4*)(encOuts + (size_t)(b * 64 + s) * 512 + kk);
        accv.x += wgt * e.x; accv.y += wgt * e.y;
        accv.z += wgt * e.z; accv.w += wgt * e.w;
    }
    *(float4*)(ctx + (size_t)b * 512 + kk) = accv;
}

// ---------------------------------------------------------------------------
// Host orchestration
// ---------------------------------------------------------------------------
extern "C" void kernel_launch(void* const* d_in, const int* in_sizes, int n_in,
                              void* d_out, int out_size)
{
    const int*   src       = (const int*)d_in[0];
    // d_in[1] = src_len (unused: all full-length; mask comes from src != 0)
    const int*   trg       = (const int*)d_in[2];
    const float* enc_emb   = (const float*)d_in[3];
    const float* enc_Wih_f = (const float*)d_in[4];
    const float* enc_Whh_f = (const float*)d_in[5];
    const float* enc_b_f   = (const float*)d_in[6];
    const float* enc_Wih_b = (const float*)d_in[7];
    const float* enc_Whh_b = (const float*)d_in[8];
    const float* enc_b_b   = (const float*)d_in[9];
    const float* enc_fc_W  = (const float*)d_in[10];
    const float* enc_fc_b  = (const float*)d_in[11];
    const float* dec_emb   = (const float*)d_in[12];
    const float* dec_Wih   = (const float*)d_in[13];
    const float* dec_Whh   = (const float*)d_in[14];
    const float* dec_b     = (const float*)d_in[15];
    const float* attn_W    = (const float*)d_in[16];
    const float* attn_b    = (const float*)d_in[17];
    const float* attn_v    = (const float*)d_in[18];
    const float* out_W     = (const float*)d_in[19];
    const float* out_b     = (const float*)d_in[20];
    float* out = (float*)d_out;

    float *Gin, *decEmb, *encOuts, *encProj, *hEnc, *cEnc, *hDec, *cDec, *ctx, *qp;
    cudaGetSymbolAddress((void**)&Gin,     g_Gin);
    cudaGetSymbolAddress((void**)&decEmb,  g_decEmb);
    cudaGetSymbolAddress((void**)&encOuts, g_encOuts);
    cudaGetSymbolAddress((void**)&encProj, g_encProj);
    cudaGetSymbolAddress((void**)&hEnc,    g_hEnc);
    cudaGetSymbolAddress((void**)&cEnc,    g_cEnc);
    cudaGetSymbolAddress((void**)&hDec,    g_hDec);
    cudaGetSymbolAddress((void**)&cDec,    g_cDec);
    cudaGetSymbolAddress((void**)&ctx,     g_ctx);
    cudaGetSymbolAddress((void**)&qp,      g_qp);

    const size_t GINSZ = (size_t)B * S * G4;      // per-direction Gin stride
    const int    BH    = B * H;

    // ---- zero recurrent state -------------------------------------------------
    zero_kernel<<<256, 256>>>(hEnc, 4 * BH);
    zero_kernel<<<256, 256>>>(cEnc, 2 * BH);
    zero_kernel<<<128, 256>>>(cDec, BH);

    // ---- precompute: encoder input gates + decoder embedding gather -----------
    embed_gemm_kernel<<<dim3(B * S / 64, G4 / 64), 256>>>(
        src, enc_emb, enc_Wih_f, E, enc_b_f, Gin, G4);
    embed_gemm_kernel<<<dim3(B * S / 64, G4 / 64), 256>>>(
        src, enc_emb, enc_Wih_b, E, enc_b_b, Gin + GINSZ, G4);
    dec_embed_gather_kernel<<<B * T, 192>>>(trg, dec_emb, decEmb);

    // ---- encoder recurrence (fwd + bwd fused via blockIdx.z) ------------------
    for (int t = 0; t < S; t++) {
        int p = t & 1;
        LstmArgs2 la;
        // forward
        la.d[0].A0 = hEnc + (size_t)(0 * 2 + p) * BH; la.d[0].ldA0 = H; la.d[0].K0 = H;
        la.d[0].A1 = nullptr; la.d[0].ldA1 = 0; la.d[0].K1 = 0;
        la.d[0].A2 = nullptr; la.d[0].ldA2 = 0; la.d[0].K2 = 0;
        la.d[0].W0 = enc_Whh_f; la.d[0].ldW0 = H;
        la.d[0].W1 = nullptr;   la.d[0].ldW1 = 0;
        la.d[0].W2 = nullptr;   la.d[0].ldW2 = 0;
        la.d[0].G = Gin + (size_t)t * G4; la.d[0].ldG = S * G4;
        la.d[0].bias = nullptr;
        la.d[0].c = cEnc;
        la.d[0].h = hEnc + (size_t)(0 * 2 + (1 - p)) * BH;
        la.d[0].h2 = encOuts + (size_t)t * EH;   // enc_outs[:, t, 0:256]
        la.d[0].ldH2 = S * EH;
        // backward (input at s = S-1-t, output slot s = S-1-t, cols 256:512)
        int sb = S - 1 - t;
        la.d[1] = la.d[0];
        la.d[1].A0 = hEnc + (size_t)(1 * 2 + p) * BH;
        la.d[1].W0 = enc_Whh_b;
        la.d[1].G = Gin + GINSZ + (size_t)sb * G4;
        la.d[1].c = cEnc + BH;
        la.d[1].h = hEnc + (size_t)(1 * 2 + (1 - p)) * BH;
        la.d[1].h2 = encOuts + (size_t)sb * EH + H;
        lstm_step_kernel<64><<<dim3(B / 64, H / 32, 2), 256>>>(la);
    }
    // final hidden states are at ping = S & 1 = 0
    const float* hF  = hEnc + (size_t)(0 * 2 + 0) * BH;
    const float* hBk = hEnc + (size_t)(1 * 2 + 0) * BH;

    // ---- h0 = tanh([h_f, h_b] @ enc_fc_W^T + enc_fc_b) -> hDec ping 0 ---------
    gemm_kernel<32, 64><<<dim3(B / 32, H / 64), 128>>>(
        hF, H, H, hBk, H, H, nullptr, 0, 0,
        enc_fc_W, EH, enc_fc_b, nullptr, 0, 1, hDec, H);

    // ---- encProj = enc_outs @ attn_W[:,256:768]^T + attn_b --------------------
    gemm_kernel<64, 64><<<dim3(B * S / 64, H / 64), 256>>>(
        encOuts, EH, EH, nullptr, 0, 0, nullptr, 0, 0,
        attn_W + H, H + EH, attn_b, nullptr, 0, 0, encProj, H);

    // ---- qp for t=0: h0 @ attn_W[:,0:256]^T -----------------------------------
    gemm_kernel<32, 64><<<dim3(B / 32, H / 64), 128>>>(
        hDec, H, H, nullptr, 0, 0, nullptr, 0, 0,
        attn_W, H + EH, nullptr, nullptr, 0, 0, qp, H);

    // ---- decoder loop ---------------------------------------------------------
    for (int t = 0; t < T; t++) {
        int p = t & 1, pn = (t + 1) & 1;
        float* hCur = hDec + (size_t)p * BH;
        float* hNew = hDec + (size_t)pn * BH;
        const float* eT = decEmb + (size_t)t * E;   // row stride T*E

        // attention -> ctx
        attn_kernel<<<B, 128>>>(src, qp, encProj, encOuts, attn_v, ctx);

        // LSTM step: gates = e@Wih[:,0:192]^T + ctx@Wih[:,192:704]^T + h@Whh^T + b
        LstmArgs2 la;
        la.d[0].A0 = eT;   la.d[0].ldA0 = T * E; la.d[0].K0 = E;
        la.d[0].A1 = ctx;  la.d[0].ldA1 = EH;    la.d[0].K1 = EH;
        la.d[0].A2 = hCur; la.d[0].ldA2 = H;     la.d[0].K2 = H;
        la.d[0].W0 = dec_Wih;     la.d[0].ldW0 = E + EH;
        la.d[0].W1 = dec_Wih + E; la.d[0].ldW1 = E + EH;
        la.d[0].W2 = dec_Whh;     la.d[0].ldW2 = H;
        la.d[0].G = nullptr; la.d[0].ldG = 0;
        la.d[0].bias = dec_b;
        la.d[0].c = cDec;
        la.d[0].h = hNew;
        la.d[0].h2 = nullptr; la.d[0].ldH2 = 0;
        la.d[1] = la.d[0];
        lstm_step_kernel<32><<<dim3(B / 32, H / 32, 1), 128>>>(la);

        // output: pred = [hNew | ctx | e] @ out_W^T + out_b
        gemm_kernel<32, 64><<<dim3(B / 32, V / 64), 128>>>(
            hNew, H, H, ctx, EH, EH, eT, T * E, E,
            out_W, H + EH + E, out_b, nullptr, 0, 0, out + (size_t)t * V, T * V);

        // qp for next step (uses hNew)
        if (t + 1 < T) {
            gemm_kernel<32, 64><<<dim3(B / 32, H / 64), 128>>>(
                hNew, H, H, nullptr, 0, 0, nullptr, 0, 0,
                attn_W, H + EH, nullptr, nullptr, 0, 0, qp, H);
        }
    }
}